// round 11
// baseline (speedup 1.0000x reference)
#include <cuda_runtime.h>

#define Bn 8
#define Cn 32
#define Hn 512
#define Wn 512
#define On 4
#define NCP (Cn / 2)            // 16 channel pairs
#define TW 64
#define TH 32
#define RRW 8                   // rows per thread
#define SSTu 66                 // smem row stride in ull (8B) elements
#define SROWS (TH + 2)
#define SNu (SROWS * SSTu)      // 2244 ull staged per channel-pair
#define K_LD 9                  // ceil(2244 / 256)
#define NTHREADS 256
#define BN_EPS 1e-5f

typedef unsigned long long ull;

__device__ double g_stats[2 * On];   // [0..3] sum, [4..7] sumsq
__device__ float  g_scale[On];
__device__ float  g_bias[On];

__device__ __forceinline__ void fma2(ull& d, ull a, ull b) {
    // packed fp32 fma (FFMA2): d.lane = a.lane*b.lane + d.lane
    asm("fma.rn.f32x2 %0, %1, %2, %0;" : "+l"(d) : "l"(a), "l"(b));
}
__device__ __forceinline__ ull pack2(float lo, float hi) {
    ull r;
    asm("mov.b64 %0, {%1, %2};" : "=l"(r) : "f"(lo), "f"(hi));
    return r;
}
__device__ __forceinline__ float2 unpack2(ull v) {
    float2 r;
    asm("mov.b64 {%0, %1}, %2;" : "=f"(r.x), "=f"(r.y) : "l"(v));
    return r;
}

__global__ void zero_stats_kernel() {
    if (threadIdx.x < 2 * On) g_stats[threadIdx.x] = 0.0;
}

// ---------------------------------------------------------------------------
// Pass 1: fused 5-tap stencil (4 directional diffs -> 1x1 conv 4C->4).
// Channel-pair interleaved FFMA2 engine:
//   smem element (h,w) = (x_c, x_{c+1}) packed ull -> every tap is an aligned
//   LDS.64; acc lanes hold even/odd-channel partial sums, summed at epilogue.
// Register-prefetch double buffering of the two input planes.
// ---------------------------------------------------------------------------
__global__ __launch_bounds__(NTHREADS, 2)
void fourdir_main(const float* __restrict__ x,
                  const float* __restrict__ wc_g,
                  float* __restrict__ out)
{
    __shared__ __align__(16) ull   sx[SNu];            // interleaved tile ~17.5 KB
    __shared__ __align__(16) ull   swt[NCP][5][On];    // paired taps NE,NW,SE,SW,C
    __shared__ float wsc[Cn][5][On];                   // scalar combined taps
    __shared__ float s_red[2 * On];

    const int tid = threadIdx.x;
    const int bxw = blockIdx.x;   // w tile (8)
    const int byh = blockIdx.y;   // h tile (16)
    const int bz  = blockIdx.z;   // batch (8)

    // --- weights: scalar combined taps, then channel-pair packing ---
    if (tid < Cn * On) {
        int c = tid >> 2, o = tid & 3;
        float w0 = wc_g[o * (4 * Cn) + 0 * Cn + c];  // NE
        float w1 = wc_g[o * (4 * Cn) + 1 * Cn + c];  // NW
        float w2 = wc_g[o * (4 * Cn) + 2 * Cn + c];  // SE
        float w3 = wc_g[o * (4 * Cn) + 3 * Cn + c];  // SW
        wsc[c][0][o] = w0;
        wsc[c][1][o] = w1;
        wsc[c][2][o] = w2;
        wsc[c][3][o] = w3;
        wsc[c][4][o] = -(w0 + w1 + w2 + w3);         // center tap
    }
    if (tid < 2 * On) s_red[tid] = 0.0f;
    __syncthreads();
    for (int idx = tid; idx < NCP * 5 * On; idx += NTHREADS) {
        int cp = idx / 20, rem = idx % 20, t = rem >> 2, o = rem & 3;
        swt[cp][t][o] = pack2(wsc[2 * cp][t][o], wsc[2 * cp + 1][t][o]);
    }
    // visibility of swt covered by the first __syncthreads in the cp loop

    const int lc  = tid & 63;      // local output col (0..63)
    const int grp = tid >> 6;      // row group (4 groups x 8 rows)
    const int i0  = grp * RRW;     // first output row (local)

    const int gh0 = byh * TH - 1;  // global row of smem row 0 (halo)
    const int gw0 = bxw * TW - 1;  // global col of smem col 0 (halo)

    // staging offsets (loop-invariant across channel pairs)
    int off[K_LD];
#pragma unroll
    for (int k = 0; k < K_LD; ++k) {
        int i = tid + k * NTHREADS;
        int r = i / SSTu;
        int cl = i - r * SSTu;
        int gh = gh0 + r;
        int gw = gw0 + cl;
        bool ok = (i < SNu) && ((unsigned)gh < (unsigned)Hn) && ((unsigned)gw < (unsigned)Wn);
        off[k] = ok ? (gh * Wn + gw) : -1;
    }

    const float* xb = x + (size_t)bz * Cn * Hn * Wn;

    // prefetch channel pair 0 (planes 0 and 1)
    float va[K_LD], vb[K_LD];
#pragma unroll
    for (int k = 0; k < K_LD; ++k) {
        va[k] = (off[k] >= 0) ? __ldg(xb + off[k]) : 0.0f;
        vb[k] = (off[k] >= 0) ? __ldg(xb + Hn * Wn + off[k]) : 0.0f;
    }

    ull acc[RRW][On];
#pragma unroll
    for (int i = 0; i < RRW; ++i)
#pragma unroll
        for (int o = 0; o < On; ++o) acc[i][o] = 0ull;

    // smem column map: output col lc -> w-1 at col lc, center lc+1, w+1 lc+2
    const ull* bp = sx + i0 * SSTu + lc;

    for (int cp = 0; cp < NCP; ++cp) {
        __syncthreads();   // previous pair's compute done (and swt visible)

        // publish current pair's interleaved tile
#pragma unroll
        for (int k = 0; k < K_LD; ++k) {
            int i = tid + k * NTHREADS;
            if (i < SNu) sx[i] = pack2(va[k], vb[k]);
        }

        // prefetch next pair (last iteration re-reads same planes; unused)
        {
            int cpn = (cp < NCP - 1) ? (cp + 1) : cp;
            const float* xa = xb + (size_t)(2 * cpn) * (Hn * Wn);
#pragma unroll
            for (int k = 0; k < K_LD; ++k) {
                va[k] = (off[k] >= 0) ? __ldg(xa + off[k]) : 0.0f;
                vb[k] = (off[k] >= 0) ? __ldg(xa + Hn * Wn + off[k]) : 0.0f;
            }
        }

        __syncthreads();   // staging visible

        const ull* wp = &swt[cp][0][0];   // broadcast LDS.64 per use

        // rolling rows: keep (L,R) of up and mid rows; load dn(L,R) + mid C
        ull upL = bp[0];
        ull upR = bp[2];
        ull mdL = bp[SSTu];
        ull mdR = bp[SSTu + 2];
#pragma unroll
        for (int i = 0; i < RRW; ++i) {
            const ull* rp = bp + (i + 2) * SSTu;
            ull dnL = rp[0];
            ull dnR = rp[2];
            ull mdC = bp[(i + 1) * SSTu + 1];
#pragma unroll
            for (int o = 0; o < On; ++o) {
                fma2(acc[i][o], wp[0 * On + o], upR);  // NE: x(h-1, w+1)
                fma2(acc[i][o], wp[1 * On + o], upL);  // NW: x(h-1, w-1)
                fma2(acc[i][o], wp[2 * On + o], dnR);  // SE: x(h+1, w+1)
                fma2(acc[i][o], wp[3 * On + o], dnL);  // SW: x(h+1, w-1)
                fma2(acc[i][o], wp[4 * On + o], mdC);  // C : x(h,   w)
            }
            upL = mdL; upR = mdR; mdL = dnL; mdR = dnR;
        }
    }

    // epilogue: horizontal add (even+odd channel partials), store y, BN stats
    float s[On] = {0, 0, 0, 0}, q[On] = {0, 0, 0, 0};
    const int wcol = bxw * TW + lc;
#pragma unroll
    for (int i = 0; i < RRW; ++i) {
        int h = byh * TH + i0 + i;
#pragma unroll
        for (int o = 0; o < On; ++o) {
            float2 p = unpack2(acc[i][o]);
            float y = p.x + p.y;
            out[(((size_t)(bz * On + o)) * Hn + h) * Wn + wcol] = y;
            s[o] += y;
            q[o] += y * y;
        }
    }
#pragma unroll
    for (int o = 0; o < On; ++o) {
        for (int offs = 16; offs; offs >>= 1) {
            s[o] += __shfl_xor_sync(0xffffffffu, s[o], offs);
            q[o] += __shfl_xor_sync(0xffffffffu, q[o], offs);
        }
    }
    if ((tid & 31) == 0) {
#pragma unroll
        for (int o = 0; o < On; ++o) {
            atomicAdd(&s_red[o], s[o]);
            atomicAdd(&s_red[On + o], q[o]);
        }
    }
    __syncthreads();
    if (tid < 2 * On) atomicAdd(&g_stats[tid], (double)s_red[tid]);
}

// ---------------------------------------------------------------------------
// Pass 2: finalize BN scale/bias (tiny)
// ---------------------------------------------------------------------------
__global__ void finalize_stats(const float* __restrict__ gamma,
                               const float* __restrict__ beta)
{
    int o = threadIdx.x;
    if (o < On) {
        const double N = (double)Bn * Hn * Wn;
        double mean = g_stats[o] / N;
        double var  = g_stats[On + o] / N - mean * mean;
        float sc = gamma[o] * (float)(1.0 / sqrt(var + (double)BN_EPS));
        g_scale[o] = sc;
        g_bias[o]  = beta[o] - (float)mean * sc;
    }
}

// ---------------------------------------------------------------------------
// Pass 3: normalize d_out in place (R9 version — measured 10.8us)
// ---------------------------------------------------------------------------
__global__ void apply_bn(float4* __restrict__ y)
{
    int i = blockIdx.x * blockDim.x + threadIdx.x;  // 2,097,152 float4s
    int c = (i >> 16) & 3;                          // 65536 float4 per (b,o) plane
    float sc = g_scale[c], bi = g_bias[c];
    float4 v = y[i];
    v.x = v.x * sc + bi;
    v.y = v.y * sc + bi;
    v.z = v.z * sc + bi;
    v.w = v.w * sc + bi;
    y[i] = v;
}

extern "C" void kernel_launch(void* const* d_in, const int* in_sizes, int n_in,
                              void* d_out, int out_size)
{
    const float* x     = (const float*)d_in[0];
    const float* w     = (const float*)d_in[1];
    const float* gamma = (const float*)d_in[2];
    const float* beta  = (const float*)d_in[3];
    float* out = (float*)d_out;

    zero_stats_kernel<<<1, 32>>>();

    dim3 grid(Wn / TW, Hn / TH, Bn);   // (8, 16, 8) = 1024 blocks
    fourdir_main<<<grid, NTHREADS>>>(x, w, out);

    finalize_stats<<<1, 32>>>(gamma, beta);

    int n4 = Bn * On * Hn * Wn / 4;    // 2,097,152 float4s
    apply_bn<<<n4 / 256, 256>>>((float4*)out);
}

// round 12
// speedup vs baseline: 1.2791x; 1.2791x over previous
#include <cuda_runtime.h>

#define Bn 8
#define Cn 32
#define Hn 512
#define Wn 512
#define On 4
#define TW 64
#define TH 16
#define RR 2                    // rows per thread
#define SST 66                  // smem row stride (floats), even -> 8B-aligned pairs
#define SROWS (TH + 2)
#define SN (SROWS * SST)        // 1188 floats staged per channel per buffer
#define K_LD 5                  // ceil(1188 / 256)
#define NTHREADS 256
#define BN_EPS 1e-5f

__device__ double g_stats[2 * On];   // [0..3] sum, [4..7] sumsq
__device__ float  g_scale[On];
__device__ float  g_bias[On];

__global__ void zero_stats_kernel() {
    if (threadIdx.x < 2 * On) g_stats[threadIdx.x] = 0.0;
}

// ---------------------------------------------------------------------------
// Pass 1: fused 5-tap stencil (4 directional diffs -> 1x1 conv 4C->4).
// Scalar fp32 engine (proven fastest), register-prefetch + DOUBLE-BUFFERED
// smem tiles -> one barrier per channel. Tile 64x16 -> 2048 blocks kills
// wave quantization (7 rounds vs ideal 6.92).
// ---------------------------------------------------------------------------
__global__ __launch_bounds__(NTHREADS, 2)
void fourdir_main(const float* __restrict__ x,
                  const float* __restrict__ wc_g,
                  float* __restrict__ out)
{
    __shared__ __align__(16) float sx[2][SN];        // double-buffered tile
    __shared__ __align__(16) float swt[Cn][5][On];   // taps: NE,NW,SE,SW,C
    __shared__ float s_red[2 * On];

    const int tid = threadIdx.x;
    const int bxw = blockIdx.x;   // w tile (8)
    const int byh = blockIdx.y;   // h tile (32)
    const int bz  = blockIdx.z;   // batch (8)

    // Build combined weights once per block (tid < 128 covers all (c,o))
    if (tid < Cn * On) {
        int c = tid >> 2, o = tid & 3;
        float w0 = wc_g[o * (4 * Cn) + 0 * Cn + c];  // NE
        float w1 = wc_g[o * (4 * Cn) + 1 * Cn + c];  // NW
        float w2 = wc_g[o * (4 * Cn) + 2 * Cn + c];  // SE
        float w3 = wc_g[o * (4 * Cn) + 3 * Cn + c];  // SW
        swt[c][0][o] = w0;
        swt[c][1][o] = w1;
        swt[c][2][o] = w2;
        swt[c][3][o] = w3;
        swt[c][4][o] = -(w0 + w1 + w2 + w3);         // center tap
    }
    if (tid < 2 * On) s_red[tid] = 0.0f;
    // visibility of swt/s_red covered by the first in-loop __syncthreads

    const int px = tid & 31;       // pair-column index (32 pairs = 64 cols)
    const int gy = tid >> 5;       // row group (8 groups x RR rows = 16 rows)
    const int lw = px << 1;        // local output col (even)
    const int i0 = gy * RR;        // first output row (local)

    const int gh0 = byh * TH - 1;  // global row of smem row 0 (halo)
    const int gw0 = bxw * TW - 1;  // global col of smem col 0 (halo)

    // staging offsets (loop-invariant across channels)
    int off[K_LD];
#pragma unroll
    for (int k = 0; k < K_LD; ++k) {
        int i = tid + k * NTHREADS;
        int r = i / SST;
        int cl = i - r * SST;
        int gh = gh0 + r;
        int gw = gw0 + cl;
        bool ok = (i < SN) && ((unsigned)gh < (unsigned)Hn) && ((unsigned)gw < (unsigned)Wn);
        off[k] = ok ? (gh * Wn + gw) : -1;
    }

    const float* xb = x + (size_t)bz * Cn * Hn * Wn;

    // prefetch channel 0 into registers
    float v[K_LD];
#pragma unroll
    for (int k = 0; k < K_LD; ++k)
        v[k] = (off[k] >= 0) ? __ldg(xb + off[k]) : 0.0f;

    float acc[RR][On][2];
#pragma unroll
    for (int r2 = 0; r2 < RR; ++r2)
#pragma unroll
        for (int o = 0; o < On; ++o) { acc[r2][o][0] = 0.0f; acc[r2][o][1] = 0.0f; }

    const int base = i0 * SST + lw;

    for (int c = 0; c < Cn; ++c) {
        float* buf = sx[c & 1];

        // publish current channel's tile into buf[c&1]
        // (safe: all warps passed sync(c-1), so compute(c-2) on this buffer done)
#pragma unroll
        for (int k = 0; k < K_LD; ++k) {
            int i = tid + k * NTHREADS;
            if (i < SN) buf[i] = v[k];
        }

        // prefetch next channel (last iteration re-reads same plane; unused)
        {
            int cn = (c < Cn - 1) ? (c + 1) : c;
            const float* xn = xb + (size_t)cn * (Hn * Wn);
#pragma unroll
            for (int k = 0; k < K_LD; ++k)
                v[k] = (off[k] >= 0) ? __ldg(xn + off[k]) : 0.0f;
        }

        __syncthreads();   // staging (and weights on c==0) visible

        // broadcast weight loads: 5 x LDS.128
        float4 wNE = *(const float4*)&swt[c][0][0];
        float4 wNW = *(const float4*)&swt[c][1][0];
        float4 wSE = *(const float4*)&swt[c][2][0];
        float4 wSW = *(const float4*)&swt[c][3][0];
        float4 wCC = *(const float4*)&swt[c][4][0];
        const float* wne = &wNE.x;
        const float* wnw = &wNW.x;
        const float* wse = &wSE.x;
        const float* wsw = &wSW.x;
        const float* wcc = &wCC.x;

        const float* bp0 = buf + base;

        // rolling rows; A = smem cols (lw, lw+1) = global (w-1, w); B = (w+1, w+2)
        float2 uA = *(const float2*)(bp0);
        float2 uB = *(const float2*)(bp0 + 2);
        float2 mA = *(const float2*)(bp0 + SST);
        float2 mB = *(const float2*)(bp0 + SST + 2);
#pragma unroll
        for (int r2 = 0; r2 < RR; ++r2) {
            const float* rp = bp0 + (r2 + 2) * SST;
            float2 dA = *(const float2*)(rp);
            float2 dB = *(const float2*)(rp + 2);
#pragma unroll
            for (int o = 0; o < On; ++o) {
                // output col w   : NE=uB.x NW=uA.x SE=dB.x SW=dA.x C=mA.y
                float a0 = acc[r2][o][0];
                a0 += wne[o] * uB.x;
                a0 += wnw[o] * uA.x;
                a0 += wse[o] * dB.x;
                a0 += wsw[o] * dA.x;
                a0 += wcc[o] * mA.y;
                acc[r2][o][0] = a0;
                // output col w+1 : NE=uB.y NW=uA.y SE=dB.y SW=dA.y C=mB.x
                float a1 = acc[r2][o][1];
                a1 += wne[o] * uB.y;
                a1 += wnw[o] * uA.y;
                a1 += wse[o] * dB.y;
                a1 += wsw[o] * dA.y;
                a1 += wcc[o] * mB.x;
                acc[r2][o][1] = a1;
            }
            uA = mA; uB = mB; mA = dA; mB = dB;
        }
    }

    // epilogue: write y, accumulate BN stats
    float s[On] = {0, 0, 0, 0}, q[On] = {0, 0, 0, 0};
    const int wcol = bxw * TW + lw;
#pragma unroll
    for (int r2 = 0; r2 < RR; ++r2) {
        int h = byh * TH + i0 + r2;
#pragma unroll
        for (int o = 0; o < On; ++o) {
            float2 y;
            y.x = acc[r2][o][0];
            y.y = acc[r2][o][1];
            *(float2*)(out + (((size_t)(bz * On + o)) * Hn + h) * Wn + wcol) = y;
            s[o] += y.x + y.y;
            q[o] += y.x * y.x + y.y * y.y;
        }
    }
#pragma unroll
    for (int o = 0; o < On; ++o) {
        for (int offs = 16; offs; offs >>= 1) {
            s[o] += __shfl_xor_sync(0xffffffffu, s[o], offs);
            q[o] += __shfl_xor_sync(0xffffffffu, q[o], offs);
        }
    }
    if ((tid & 31) == 0) {
#pragma unroll
        for (int o = 0; o < On; ++o) {
            atomicAdd(&s_red[o], s[o]);
            atomicAdd(&s_red[On + o], q[o]);
        }
    }
    __syncthreads();
    if (tid < 2 * On) atomicAdd(&g_stats[tid], (double)s_red[tid]);
}

// ---------------------------------------------------------------------------
// Pass 2: finalize BN scale/bias (tiny)
// ---------------------------------------------------------------------------
__global__ void finalize_stats(const float* __restrict__ gamma,
                               const float* __restrict__ beta)
{
    int o = threadIdx.x;
    if (o < On) {
        const double N = (double)Bn * Hn * Wn;
        double mean = g_stats[o] / N;
        double var  = g_stats[On + o] / N - mean * mean;
        float sc = gamma[o] * (float)(1.0 / sqrt(var + (double)BN_EPS));
        g_scale[o] = sc;
        g_bias[o]  = beta[o] - (float)mean * sc;
    }
}

// ---------------------------------------------------------------------------
// Pass 3: normalize d_out in place. Two far-apart float4 streams per thread
// (MLP=2) — conservative upgrade of the proven 10.8us version.
// ---------------------------------------------------------------------------
#define N4HALF (Bn * On * Hn * Wn / 8)   // 1,048,576 float4s per stream
__global__ void apply_bn(float4* __restrict__ y)
{
    int i = blockIdx.x * blockDim.x + threadIdx.x;  // 0 .. N4HALF-1
    int j = i + N4HALF;
    float4 a = y[i];
    float4 b = y[j];
    int ca = (i >> 16) & 3;                         // 65536 float4 per (b,o) plane
    int cb = (j >> 16) & 3;
    float sa = g_scale[ca], ba = g_bias[ca];
    float sb = g_scale[cb], bb = g_bias[cb];
    a.x = a.x * sa + ba;  a.y = a.y * sa + ba;
    a.z = a.z * sa + ba;  a.w = a.w * sa + ba;
    b.x = b.x * sb + bb;  b.y = b.y * sb + bb;
    b.z = b.z * sb + bb;  b.w = b.w * sb + bb;
    y[i] = a;
    y[j] = b;
}

extern "C" void kernel_launch(void* const* d_in, const int* in_sizes, int n_in,
                              void* d_out, int out_size)
{
    const float* x     = (const float*)d_in[0];
    const float* w     = (const float*)d_in[1];
    const float* gamma = (const float*)d_in[2];
    const float* beta  = (const float*)d_in[3];
    float* out = (float*)d_out;

    zero_stats_kernel<<<1, 32>>>();

    dim3 grid(Wn / TW, Hn / TH, Bn);   // (8, 32, 8) = 2048 blocks
    fourdir_main<<<grid, NTHREADS>>>(x, w, out);

    finalize_stats<<<1, 32>>>(gamma, beta);

    apply_bn<<<N4HALF / 256, 256>>>((float4*)out);
}

// round 13
// speedup vs baseline: 1.5034x; 1.1753x over previous
#include <cuda_runtime.h>

#define Bn 8
#define Cn 32
#define Hn 512
#define Wn 512
#define On 4
#define TW 64
#define TH 32
#define RR 4                    // output rows per thread
#define NROWS (RR + 2)          // loaded rows per thread (halo)
#define NTHREADS 256
#define BN_EPS 1e-5f
#define HW (Hn * Wn)

__device__ double g_stats[2 * On];   // [0..3] sum, [4..7] sumsq
__device__ float  g_scale[On];
__device__ float  g_bias[On];

__global__ void zero_stats_kernel() {
    if (threadIdx.x < 2 * On) g_stats[threadIdx.x] = 0.0;
}

// ---------------------------------------------------------------------------
// Pass 1: fused 5-tap stencil (4 directional diffs -> 1x1 conv 4C->4).
// Barrier-free engine: each lane owns 2 columns; horizontal neighbors come
// from warp shuffles; tile-edge columns from predicated halo loads in lanes
// 0/31. No smem staging, no per-channel barriers. Channel-ahead prefetch with
// manual A/B register double-buffering.
// ---------------------------------------------------------------------------
__global__ __launch_bounds__(NTHREADS, 2)
void fourdir_main(const float* __restrict__ x,
                  const float* __restrict__ wc_g,
                  float* __restrict__ out)
{
    __shared__ __align__(16) float swt[Cn][5][On];   // taps: NE,NW,SE,SW,C
    __shared__ float s_red[2 * On];

    const int tid = threadIdx.x;
    const int bxw = blockIdx.x;   // w tile (8)
    const int byh = blockIdx.y;   // h tile (16)
    const int bz  = blockIdx.z;   // batch (8)

    // Build combined weights once per block
    if (tid < Cn * On) {
        int c = tid >> 2, o = tid & 3;
        float w0 = wc_g[o * (4 * Cn) + 0 * Cn + c];  // NE
        float w1 = wc_g[o * (4 * Cn) + 1 * Cn + c];  // NW
        float w2 = wc_g[o * (4 * Cn) + 2 * Cn + c];  // SE
        float w3 = wc_g[o * (4 * Cn) + 3 * Cn + c];  // SW
        swt[c][0][o] = w0;
        swt[c][1][o] = w1;
        swt[c][2][o] = w2;
        swt[c][3][o] = w3;
        swt[c][4][o] = -(w0 + w1 + w2 + w3);         // center tap
    }
    if (tid < 2 * On) s_red[tid] = 0.0f;
    __syncthreads();   // weights + s_red visible (only barrier before epilogue)

    const int lane = tid & 31;
    const int g    = tid >> 5;            // warp id = row group
    const int cw   = bxw * TW + 2 * lane; // global col of this lane's even col
    const int rb   = byh * TH + g * RR;   // first output row (global)

    // per-row offsets & validity (reused across all channels)
    int  rowoff[NROWS];
    bool valid[NROWS];
#pragma unroll
    for (int r = 0; r < NROWS; ++r) {
        int lr = rb - 1 + r;
        valid[r]  = ((unsigned)lr < (unsigned)Hn);
        rowoff[r] = lr * Wn + cw;
    }
    // halo column: lane 0 loads cw-1 (left tile halo), lane 31 loads cw+2 (right)
    const bool hp   = (lane == 0) ? (bxw > 0) : ((lane == 31) ? (bxw < 7) : false);
    const int  hoff = (lane == 0) ? -1 : 2;

    const float* xb = x + (size_t)bz * Cn * HW;

    float2 vA[NROWS]; float hA[NROWS];
    float2 vB[NROWS]; float hB[NROWS];

    auto loadbuf = [&](float2 (&v)[NROWS], float (&h)[NROWS], const float* cp) {
#pragma unroll
        for (int r = 0; r < NROWS; ++r) {
            if (valid[r]) {
                v[r] = *(const float2*)(cp + rowoff[r]);
                h[r] = hp ? __ldg(cp + rowoff[r] + hoff) : 0.0f;
            } else {
                v[r] = make_float2(0.0f, 0.0f);
                h[r] = 0.0f;
            }
        }
    };

    float acc[RR][On][2];
#pragma unroll
    for (int i = 0; i < RR; ++i)
#pragma unroll
        for (int o = 0; o < On; ++o) { acc[i][o][0] = 0.0f; acc[i][o][1] = 0.0f; }

    auto compute = [&](const float2 (&v)[NROWS], const float (&h)[NROWS], int c) {
        float4 wNE = *(const float4*)&swt[c][0][0];
        float4 wNW = *(const float4*)&swt[c][1][0];
        float4 wSE = *(const float4*)&swt[c][2][0];
        float4 wSW = *(const float4*)&swt[c][3][0];
        float4 wCC = *(const float4*)&swt[c][4][0];
        const float* wne = &wNE.x;
        const float* wnw = &wNW.x;
        const float* wse = &wSE.x;
        const float* wsw = &wSW.x;
        const float* wcc = &wCC.x;

        float L[NROWS], R[NROWS];
#pragma unroll
        for (int r = 0; r < NROWS; ++r) {
            L[r] = __shfl_up_sync(0xffffffffu, v[r].y, 1);   // col cw-1
            if (lane == 0) L[r] = h[r];
            R[r] = __shfl_down_sync(0xffffffffu, v[r].x, 1); // col cw+2
            if (lane == 31) R[r] = h[r];
        }
#pragma unroll
        for (int i = 0; i < RR; ++i) {
            const int up = i, mid = i + 1, dn = i + 2;
#pragma unroll
            for (int o = 0; o < On; ++o) {
                // even col (w = cw): w+1 = v.y, w-1 = L, center = v[mid].x
                float a0 = acc[i][o][0];
                a0 += wne[o] * v[up].y;
                a0 += wnw[o] * L[up];
                a0 += wse[o] * v[dn].y;
                a0 += wsw[o] * L[dn];
                a0 += wcc[o] * v[mid].x;
                acc[i][o][0] = a0;
                // odd col (w = cw+1): w+1 = R, w-1 = v.x, center = v[mid].y
                float a1 = acc[i][o][1];
                a1 += wne[o] * R[up];
                a1 += wnw[o] * v[up].x;
                a1 += wse[o] * R[dn];
                a1 += wsw[o] * v[dn].x;
                a1 += wcc[o] * v[mid].y;
                acc[i][o][1] = a1;
            }
        }
    };

    // manual A/B double-buffered channel loop (channel-ahead prefetch)
    loadbuf(vA, hA, xb);                                   // channel 0
#pragma unroll 1
    for (int c = 0; c < Cn; c += 2) {
        loadbuf(vB, hB, xb + (size_t)(c + 1) * HW);        // prefetch c+1
        compute(vA, hA, c);
        const float* xn = xb + (size_t)((c + 2 < Cn) ? c + 2 : c) * HW;
        loadbuf(vA, hA, xn);                               // prefetch c+2
        compute(vB, hB, c + 1);
    }

    // epilogue: write y, accumulate BN stats
    float s[On] = {0, 0, 0, 0}, q[On] = {0, 0, 0, 0};
#pragma unroll
    for (int i = 0; i < RR; ++i) {
        int hrow = rb + i;
#pragma unroll
        for (int o = 0; o < On; ++o) {
            float2 y;
            y.x = acc[i][o][0];
            y.y = acc[i][o][1];
            *(float2*)(out + (((size_t)(bz * On + o)) * Hn + hrow) * Wn + cw) = y;
            s[o] += y.x + y.y;
            q[o] += y.x * y.x + y.y * y.y;
        }
    }
#pragma unroll
    for (int o = 0; o < On; ++o) {
        for (int offs = 16; offs; offs >>= 1) {
            s[o] += __shfl_xor_sync(0xffffffffu, s[o], offs);
            q[o] += __shfl_xor_sync(0xffffffffu, q[o], offs);
        }
    }
    if (lane == 0) {
#pragma unroll
        for (int o = 0; o < On; ++o) {
            atomicAdd(&s_red[o], s[o]);
            atomicAdd(&s_red[On + o], q[o]);
        }
    }
    __syncthreads();
    if (tid < 2 * On) atomicAdd(&g_stats[tid], (double)s_red[tid]);
}

// ---------------------------------------------------------------------------
// Pass 2: finalize BN scale/bias (tiny)
// ---------------------------------------------------------------------------
__global__ void finalize_stats(const float* __restrict__ gamma,
                               const float* __restrict__ beta)
{
    int o = threadIdx.x;
    if (o < On) {
        const double N = (double)Bn * Hn * Wn;
        double mean = g_stats[o] / N;
        double var  = g_stats[On + o] / N - mean * mean;
        float sc = gamma[o] * (float)(1.0 / sqrt(var + (double)BN_EPS));
        g_scale[o] = sc;
        g_bias[o]  = beta[o] - (float)mean * sc;
    }
}

// ---------------------------------------------------------------------------
// Pass 3: normalize d_out in place (proven ~11us form)
// ---------------------------------------------------------------------------
__global__ void apply_bn(float4* __restrict__ y)
{
    int i = blockIdx.x * blockDim.x + threadIdx.x;  // 2,097,152 float4s
    int c = (i >> 16) & 3;                          // 65536 float4 per (b,o) plane
    float sc = g_scale[c], bi = g_bias[c];
    float4 v = y[i];
    v.x = v.x * sc + bi;
    v.y = v.y * sc + bi;
    v.z = v.z * sc + bi;
    v.w = v.w * sc + bi;
    y[i] = v;
}

extern "C" void kernel_launch(void* const* d_in, const int* in_sizes, int n_in,
                              void* d_out, int out_size)
{
    const float* x     = (const float*)d_in[0];
    const float* w     = (const float*)d_in[1];
    const float* gamma = (const float*)d_in[2];
    const float* beta  = (const float*)d_in[3];
    float* out = (float*)d_out;

    zero_stats_kernel<<<1, 32>>>();

    dim3 grid(Wn / TW, Hn / TH, Bn);   // (8, 16, 8) = 1024 blocks
    fourdir_main<<<grid, NTHREADS>>>(x, w, out);

    finalize_stats<<<1, 32>>>(gamma, beta);

    int n4 = Bn * On * Hn * Wn / 4;    // 2,097,152 float4s
    apply_bn<<<n4 / 256, 256>>>((float4*)out);
}

// round 14
// speedup vs baseline: 1.5107x; 1.0049x over previous
#include <cuda_runtime.h>

#define Bn 8
#define Cn 32
#define Hn 512
#define Wn 512
#define On 4
#define TW 64
#define TH 32
#define RR 4                    // output rows per thread
#define NROWS (RR + 2)          // loaded rows per thread (halo)
#define NTHREADS 256
#define BN_EPS 1e-5f
#define HW (Hn * Wn)

__device__ double g_stats[2 * On];   // [0..3] sum, [4..7] sumsq
__device__ float  g_scale[On];
__device__ float  g_bias[On];

__global__ void zero_stats_kernel() {
    if (threadIdx.x < 2 * On) g_stats[threadIdx.x] = 0.0;
}

// ---------------------------------------------------------------------------
// Pass 1: fused 5-tap stencil (4 directional diffs -> 1x1 conv 4C->4).
// Barrier-free engine: each lane owns 2 columns; horizontal neighbors come
// from warp shuffles; tile-edge columns from predicated halo loads in lanes
// 0/31. No smem staging, no per-channel barriers. Channel-ahead prefetch with
// manual A/B register double-buffering.
// ---------------------------------------------------------------------------
__global__ __launch_bounds__(NTHREADS, 2)
void fourdir_main(const float* __restrict__ x,
                  const float* __restrict__ wc_g,
                  float* __restrict__ out)
{
    __shared__ __align__(16) float swt[Cn][5][On];   // taps: NE,NW,SE,SW,C
    __shared__ float s_red[2 * On];

    const int tid = threadIdx.x;
    const int bxw = blockIdx.x;   // w tile (8)
    const int byh = blockIdx.y;   // h tile (16)
    const int bz  = blockIdx.z;   // batch (8)

    // Build combined weights once per block
    if (tid < Cn * On) {
        int c = tid >> 2, o = tid & 3;
        float w0 = wc_g[o * (4 * Cn) + 0 * Cn + c];  // NE
        float w1 = wc_g[o * (4 * Cn) + 1 * Cn + c];  // NW
        float w2 = wc_g[o * (4 * Cn) + 2 * Cn + c];  // SE
        float w3 = wc_g[o * (4 * Cn) + 3 * Cn + c];  // SW
        swt[c][0][o] = w0;
        swt[c][1][o] = w1;
        swt[c][2][o] = w2;
        swt[c][3][o] = w3;
        swt[c][4][o] = -(w0 + w1 + w2 + w3);         // center tap
    }
    if (tid < 2 * On) s_red[tid] = 0.0f;
    __syncthreads();   // weights + s_red visible (only barrier before epilogue)

    const int lane = tid & 31;
    const int g    = tid >> 5;            // warp id = row group
    const int cw   = bxw * TW + 2 * lane; // global col of this lane's even col
    const int rb   = byh * TH + g * RR;   // first output row (global)

    // per-row offsets & validity (reused across all channels)
    int  rowoff[NROWS];
    bool valid[NROWS];
#pragma unroll
    for (int r = 0; r < NROWS; ++r) {
        int lr = rb - 1 + r;
        valid[r]  = ((unsigned)lr < (unsigned)Hn);
        rowoff[r] = lr * Wn + cw;
    }
    // halo column: lane 0 loads cw-1 (left tile halo), lane 31 loads cw+2 (right)
    const bool hp   = (lane == 0) ? (bxw > 0) : ((lane == 31) ? (bxw < 7) : false);
    const int  hoff = (lane == 0) ? -1 : 2;

    const float* xb = x + (size_t)bz * Cn * HW;

    float2 vA[NROWS]; float hA[NROWS];
    float2 vB[NROWS]; float hB[NROWS];

    auto loadbuf = [&](float2 (&v)[NROWS], float (&h)[NROWS], const float* cp) {
#pragma unroll
        for (int r = 0; r < NROWS; ++r) {
            if (valid[r]) {
                v[r] = *(const float2*)(cp + rowoff[r]);
                h[r] = hp ? __ldg(cp + rowoff[r] + hoff) : 0.0f;
            } else {
                v[r] = make_float2(0.0f, 0.0f);
                h[r] = 0.0f;
            }
        }
    };

    float acc[RR][On][2];
#pragma unroll
    for (int i = 0; i < RR; ++i)
#pragma unroll
        for (int o = 0; o < On; ++o) { acc[i][o][0] = 0.0f; acc[i][o][1] = 0.0f; }

    auto compute = [&](const float2 (&v)[NROWS], const float (&h)[NROWS], int c) {
        float4 wNE = *(const float4*)&swt[c][0][0];
        float4 wNW = *(const float4*)&swt[c][1][0];
        float4 wSE = *(const float4*)&swt[c][2][0];
        float4 wSW = *(const float4*)&swt[c][3][0];
        float4 wCC = *(const float4*)&swt[c][4][0];
        const float* wne = &wNE.x;
        const float* wnw = &wNW.x;
        const float* wse = &wSE.x;
        const float* wsw = &wSW.x;
        const float* wcc = &wCC.x;

        float L[NROWS], R[NROWS];
#pragma unroll
        for (int r = 0; r < NROWS; ++r) {
            L[r] = __shfl_up_sync(0xffffffffu, v[r].y, 1);   // col cw-1
            if (lane == 0) L[r] = h[r];
            R[r] = __shfl_down_sync(0xffffffffu, v[r].x, 1); // col cw+2
            if (lane == 31) R[r] = h[r];
        }
#pragma unroll
        for (int i = 0; i < RR; ++i) {
            const int up = i, mid = i + 1, dn = i + 2;
#pragma unroll
            for (int o = 0; o < On; ++o) {
                // even col (w = cw): w+1 = v.y, w-1 = L, center = v[mid].x
                float a0 = acc[i][o][0];
                a0 += wne[o] * v[up].y;
                a0 += wnw[o] * L[up];
                a0 += wse[o] * v[dn].y;
                a0 += wsw[o] * L[dn];
                a0 += wcc[o] * v[mid].x;
                acc[i][o][0] = a0;
                // odd col (w = cw+1): w+1 = R, w-1 = v.x, center = v[mid].y
                float a1 = acc[i][o][1];
                a1 += wne[o] * R[up];
                a1 += wnw[o] * v[up].x;
                a1 += wse[o] * R[dn];
                a1 += wsw[o] * v[dn].x;
                a1 += wcc[o] * v[mid].y;
                acc[i][o][1] = a1;
            }
        }
    };

    // manual A/B double-buffered channel loop (channel-ahead prefetch)
    loadbuf(vA, hA, xb);                                   // channel 0
#pragma unroll 1
    for (int c = 0; c < Cn; c += 2) {
        loadbuf(vB, hB, xb + (size_t)(c + 1) * HW);        // prefetch c+1
        compute(vA, hA, c);
        const float* xn = xb + (size_t)((c + 2 < Cn) ? c + 2 : c) * HW;
        loadbuf(vA, hA, xn);                               // prefetch c+2
        compute(vB, hB, c + 1);
    }

    // epilogue: write y, accumulate BN stats
    float s[On] = {0, 0, 0, 0}, q[On] = {0, 0, 0, 0};
#pragma unroll
    for (int i = 0; i < RR; ++i) {
        int hrow = rb + i;
#pragma unroll
        for (int o = 0; o < On; ++o) {
            float2 y;
            y.x = acc[i][o][0];
            y.y = acc[i][o][1];
            *(float2*)(out + (((size_t)(bz * On + o)) * Hn + hrow) * Wn + cw) = y;
            s[o] += y.x + y.y;
            q[o] += y.x * y.x + y.y * y.y;
        }
    }
#pragma unroll
    for (int o = 0; o < On; ++o) {
        for (int offs = 16; offs; offs >>= 1) {
            s[o] += __shfl_xor_sync(0xffffffffu, s[o], offs);
            q[o] += __shfl_xor_sync(0xffffffffu, q[o], offs);
        }
    }
    if (lane == 0) {
#pragma unroll
        for (int o = 0; o < On; ++o) {
            atomicAdd(&s_red[o], s[o]);
            atomicAdd(&s_red[On + o], q[o]);
        }
    }
    __syncthreads();
    if (tid < 2 * On) atomicAdd(&g_stats[tid], (double)s_red[tid]);
}

// ---------------------------------------------------------------------------
// Pass 2: finalize BN scale/bias (tiny)
// ---------------------------------------------------------------------------
__global__ void finalize_stats(const float* __restrict__ gamma,
                               const float* __restrict__ beta)
{
    int o = threadIdx.x;
    if (o < On) {
        const double N = (double)Bn * Hn * Wn;
        double mean = g_stats[o] / N;
        double var  = g_stats[On + o] / N - mean * mean;
        float sc = gamma[o] * (float)(1.0 / sqrt(var + (double)BN_EPS));
        g_scale[o] = sc;
        g_bias[o]  = beta[o] - (float)mean * sc;
    }
}

// ---------------------------------------------------------------------------
// Pass 3: normalize d_out in place (proven ~11us form)
// ---------------------------------------------------------------------------
__global__ void apply_bn(float4* __restrict__ y)
{
    int i = blockIdx.x * blockDim.x + threadIdx.x;  // 2,097,152 float4s
    int c = (i >> 16) & 3;                          // 65536 float4 per (b,o) plane
    float sc = g_scale[c], bi = g_bias[c];
    float4 v = y[i];
    v.x = v.x * sc + bi;
    v.y = v.y * sc + bi;
    v.z = v.z * sc + bi;
    v.w = v.w * sc + bi;
    y[i] = v;
}

extern "C" void kernel_launch(void* const* d_in, const int* in_sizes, int n_in,
                              void* d_out, int out_size)
{
    const float* x     = (const float*)d_in[0];
    const float* w     = (const float*)d_in[1];
    const float* gamma = (const float*)d_in[2];
    const float* beta  = (const float*)d_in[3];
    float* out = (float*)d_out;

    zero_stats_kernel<<<1, 32>>>();

    dim3 grid(Wn / TW, Hn / TH, Bn);   // (8, 16, 8) = 1024 blocks
    fourdir_main<<<grid, NTHREADS>>>(x, w, out);

    finalize_stats<<<1, 32>>>(gamma, beta);

    int n4 = Bn * On * Hn * Wn / 4;    // 2,097,152 float4s
    apply_bn<<<n4 / 256, 256>>>((float4*)out);
}